// round 3
// baseline (speedup 1.0000x reference)
#include <cuda_runtime.h>

// actions: [B=4096, T=256, A=64] fp32
// out[b,t,a] = x[b,0,a] + sum_{s=1..t} clip(x[b,s,a]-x[b,s-1,a], -0.5, 0.5)
//
// Block-local segmented scan, occupancy-optimized:
//   1 block per b. 512 threads = 32 t-segments x 16 a4-columns.
//   SEGLEN=8 keeps the register file small (~60 regs) -> 32 warps/SM.
//   Segment-boundary values passed through smem (no extra global reads).
//   Exactly 1 global load + 1 global store per element.

#define A4     16   // float4 per A-dim (64 floats)
#define SEGS   32
#define SEGLEN 8
#define TSTEPS 256

__device__ __forceinline__ float clip05(float d) {
    return fminf(fmaxf(d, -0.5f), 0.5f);
}

__device__ __forceinline__ float4 f4add(float4 a, float4 b) {
    return make_float4(a.x + b.x, a.y + b.y, a.z + b.z, a.w + b.w);
}

__global__ void __launch_bounds__(512, 2) smoothness_scan_kernel(
    const float4* __restrict__ x, float4* __restrict__ y)
{
    const int b   = blockIdx.x;
    const int tid = threadIdx.x;
    const int seg = tid >> 4;     // 0..31
    const int a4  = tid & 15;     // 0..15

    const float4* xb = x + (long)b * (TSTEPS * A4);
    float4*       yb = y + (long)b * (TSTEPS * A4);

    __shared__ float4 s_last[SEGS][A4];  // raw last element of each segment
    __shared__ float4 s_sum[SEGS][A4];   // per-segment clipped-diff totals
    __shared__ float4 s_x0[A4];          // x[b, 0, :]

    const int t0 = seg * SEGLEN;

    // Batch all loads up front for memory-level parallelism (8 in flight/thread).
    float4 c[SEGLEN];
    #pragma unroll
    for (int j = 0; j < SEGLEN; ++j)
        c[j] = xb[(t0 + j) * A4 + a4];

    // Publish segment boundary (raw input) + base row.
    s_last[seg][a4] = c[SEGLEN - 1];
    if (seg == 0) s_x0[a4] = c[0];
    __syncthreads();

    float4 prev = (seg > 0) ? s_last[seg - 1][a4] : c[0];

    // Local prefix of clipped diffs within the segment, in-place into c[].
    float4 acc = make_float4(0.f, 0.f, 0.f, 0.f);
    #pragma unroll
    for (int j = 0; j < SEGLEN; ++j) {
        float4 cur = c[j];
        if (seg == 0 && j == 0) {
            c[0] = acc;                  // local prefix at t=0 is 0
            prev = cur;
            continue;
        }
        acc.x += clip05(cur.x - prev.x);
        acc.y += clip05(cur.y - prev.y);
        acc.z += clip05(cur.z - prev.z);
        acc.w += clip05(cur.w - prev.w);
        prev = cur;
        c[j] = acc;
    }
    s_sum[seg][a4] = acc;
    __syncthreads();

    // Exclusive prefix over segment totals + base x[b,0,:].
    float4 offset = s_x0[a4];
    #pragma unroll
    for (int k = 0; k < SEGS; ++k) {
        if (k < seg) offset = f4add(offset, s_sum[k][a4]);
    }

    // Add offset and store.
    #pragma unroll
    for (int j = 0; j < SEGLEN; ++j)
        yb[(t0 + j) * A4 + a4] = f4add(offset, c[j]);
}

extern "C" void kernel_launch(void* const* d_in, const int* in_sizes, int n_in,
                              void* d_out, int out_size) {
    const float4* x = (const float4*)d_in[0];
    float4* y = (float4*)d_out;
    smoothness_scan_kernel<<<4096, 512>>>(x, y);
}